// round 16
// baseline (speedup 1.0000x reference)
#include <cuda_runtime.h>
#include <cuda_fp16.h>
#include <math.h>

#define NN 50000
#define NE 800000
#define NG 64
#define SCAN_B ((NN + 255) / 256)
#define TM ((NN + 127) / 128)   // 391 m-tiles

typedef unsigned long long u64;
typedef unsigned int u32;

// ---------------- scratch (device globals; no allocation allowed) -------------
__device__ __half g_h16[(size_t)NN * 256];   // layer activations, fp16
__device__ __half g_A16[(size_t)NN * 256];   // aggregated activations (GEMM A), fp16
__device__ float g_dinv[NN];
__device__ int   g_cnt[NN];
__device__ int   g_off[NN + 1];
__device__ int   g_cur[NN];
__device__ int   g_bsum[SCAN_B];
__device__ int   g_csr_src[NE];
__device__ float g_csr_norm[NE];
__device__ float g_pool[NG * 256];
// fp16 weights per layer (0:W2 K=128, 1:W3, 2:W4)
__device__ unsigned short g_Wh[3][256 * 256];

// ---------------- PTX helpers ---------------------------------------------------

__device__ __forceinline__ u32 smem_u32(const void* p) {
    u32 a;
    asm("{ .reg .u64 t; cvta.to.shared.u64 t, %1; cvt.u32.u64 %0, t; }" : "=r"(a) : "l"(p));
    return a;
}
__device__ __forceinline__ void ldmx4(u32* r, u32 a) {
    asm volatile("ldmatrix.sync.aligned.m8n8.x4.shared.b16 {%0,%1,%2,%3}, [%4];"
                 : "=r"(r[0]), "=r"(r[1]), "=r"(r[2]), "=r"(r[3]) : "r"(a));
}
__device__ __forceinline__ void ldmx4t(u32* r, u32 a) {
    asm volatile("ldmatrix.sync.aligned.m8n8.x4.trans.shared.b16 {%0,%1,%2,%3}, [%4];"
                 : "=r"(r[0]), "=r"(r[1]), "=r"(r[2]), "=r"(r[3]) : "r"(a));
}
__device__ __forceinline__ void mma16816h(float* c, const u32* a, const u32* b) {
    asm volatile(
        "mma.sync.aligned.m16n8k16.row.col.f32.f16.f16.f32 "
        "{%0,%1,%2,%3}, {%4,%5,%6,%7}, {%8,%9}, {%0,%1,%2,%3};"
        : "+f"(c[0]), "+f"(c[1]), "+f"(c[2]), "+f"(c[3])
        : "r"(a[0]), "r"(a[1]), "r"(a[2]), "r"(a[3]), "r"(b[0]), "r"(b[1]));
}
__device__ __forceinline__ void cp16(u32 dst, const void* src, u32 sz) {
    asm volatile("cp.async.cg.shared.global [%0], [%1], 16, %2;"
                 :: "r"(dst), "l"(src), "r"(sz) : "memory");
}
__device__ __forceinline__ void cp_commit() {
    asm volatile("cp.async.commit_group;" ::: "memory");
}
template <int N>
__device__ __forceinline__ void cp_wait() {
    asm volatile("cp.async.wait_group %0;" :: "n"(N) : "memory");
}
__device__ __forceinline__ float h2f_bits(unsigned short bits) {
    __half h = __ushort_as_half(bits);
    return __half2float(h);
}

// ---------------- preprocessing ----------------------------------------------

__global__ void count_kernel(const int* __restrict__ dst) {
    int e = blockIdx.x * blockDim.x + threadIdx.x;
    if (e < NE) atomicAdd(&g_cnt[dst[e]], 1);
}

__global__ void scan1_kernel() {
    __shared__ int s[256];
    int tid = threadIdx.x;
    int idx = blockIdx.x * 256 + tid;
    int v = (idx < NN) ? g_cnt[idx] : 0;
    s[tid] = v;
    __syncthreads();
#pragma unroll
    for (int o = 1; o < 256; o <<= 1) {
        int t = (tid >= o) ? s[tid - o] : 0;
        __syncthreads();
        s[tid] += t;
        __syncthreads();
    }
    if (idx < NN) g_off[idx] = s[tid] - v;
    if (tid == 255) g_bsum[blockIdx.x] = s[255];
}

// finalize with inline block-base reduction (replaces scan2)
__global__ void finalize_kernel() {
    __shared__ int s[256];
    int tid = threadIdx.x;
    int b = blockIdx.x;
    int part = (tid < SCAN_B && tid < b) ? g_bsum[tid] : 0;
    s[tid] = part;
    __syncthreads();
#pragma unroll
    for (int o = 128; o > 0; o >>= 1) {
        if (tid < o) s[tid] += s[tid + o];
        __syncthreads();
    }
    int base = s[0];

    int v = b * 256 + tid;
    if (v < NN) {
        int off = g_off[v] + base;
        g_off[v] = off;
        g_cur[v] = off;
        g_dinv[v] = rsqrtf((float)g_cnt[v] + 1.0f);
    }
    if (v < NG * 256) g_pool[v] = -INFINITY;
    if (v == 0) g_off[NN] = NE;
}

__global__ void fill_kernel(const int* __restrict__ src,
                            const int* __restrict__ dst) {
    int e = blockIdx.x * blockDim.x + threadIdx.x;
    if (e < NE) {
        int s = src[e];
        int d = dst[e];
        int pos = atomicAdd(&g_cur[d], 1);
        g_csr_src[pos] = s;
        g_csr_norm[pos] = g_dinv[s] * g_dinv[d];
    }
}

// ---------------- weight conversion (fp16) + zero counters ----------------------

__global__ void conv_w_all(const float* __restrict__ W2,
                           const float* __restrict__ W3,
                           const float* __restrict__ W4) {
    int i = blockIdx.x * 256 + threadIdx.x;
    if (i < NN) g_cnt[i] = 0;
    const float* W;
    unsigned short* dh;
    int off;
    if (i < 32768)       { W = W2; off = i;           dh = g_Wh[0]; }
    else if (i < 98304)  { W = W3; off = i - 32768;   dh = g_Wh[1]; }
    else if (i < 163840) { W = W4; off = i - 98304;   dh = g_Wh[2]; }
    else return;
    dh[off] = __half_as_ushort(__float2half_rn(W[off]));
}

// ---------------- fused layer 1: agg9 + [N,9]@[9,128] + bias + relu -> fp16 -----

__global__ __launch_bounds__(256) void layer1_kernel(const float* __restrict__ x,
                                                     const float* __restrict__ W1,
                                                     const float* __restrict__ b1) {
    __shared__ float Ws[9 * 128];
    __shared__ float Bs[128];
    int tid = threadIdx.x;
    for (int i = tid; i < 9 * 128; i += 256) Ws[i] = W1[i];
    if (tid < 128) Bs[tid] = b1[tid];
    __syncthreads();

    int warp = (blockIdx.x * 256 + tid) >> 5;
    int lane = tid & 31;
    if (warp >= NN) return;
    int v = warp;
    float dv = g_dinv[v];
    float acc = 0.f;
    if (lane < 9) acc = dv * dv * x[v * 9 + lane];
    int e0 = g_off[v], e1 = g_off[v + 1];
    for (int e = e0; e < e1; e++) {
        int s = g_csr_src[e];
        float nrm = g_csr_norm[e];
        if (lane < 9) acc += nrm * x[s * 9 + lane];
    }
    float ak[9];
#pragma unroll
    for (int k = 0; k < 9; k++) ak[k] = __shfl_sync(0xffffffffu, acc, k);

    int f = lane * 4;
    float o0 = Bs[f], o1 = Bs[f + 1], o2 = Bs[f + 2], o3 = Bs[f + 3];
#pragma unroll
    for (int k = 0; k < 9; k++) {
        float a = ak[k];
        const float* wr = &Ws[k * 128 + f];
        o0 += a * wr[0]; o1 += a * wr[1]; o2 += a * wr[2]; o3 += a * wr[3];
    }
    o0 = fmaxf(o0, 0.f); o1 = fmaxf(o1, 0.f);
    o2 = fmaxf(o2, 0.f); o3 = fmaxf(o3, 0.f);
    __half2* dst = (__half2*)(g_h16 + (size_t)v * 128 + f);
    dst[0] = __floats2half2_rn(o0, o1);
    dst[1] = __floats2half2_rn(o2, o3);
}

// ---------------- agg F=128: warp per node (x8 unroll) ---------------------------

__global__ __launch_bounds__(256) void agg128_kernel() {
    int warp = (blockIdx.x * blockDim.x + threadIdx.x) >> 5;
    int lane = threadIdx.x & 31;
    if (warp >= NN) return;
    const int v = warp;
    const uint2* H2 = (const uint2*)g_h16;

    float acc[4];
    float dv = g_dinv[v];
    float w = dv * dv;
    {
        uint2 q = H2[(size_t)v * 32 + lane];
        __half2* h = (__half2*)&q;
#pragma unroll
        for (int j = 0; j < 2; j++) {
            float2 f2 = __half22float2(h[j]);
            acc[2 * j] = w * f2.x; acc[2 * j + 1] = w * f2.y;
        }
    }

    int e0 = g_off[v], e1 = g_off[v + 1];
    int e = e0;
    for (; e + 8 <= e1; e += 8) {
        int si[8]; float ni[8];
#pragma unroll
        for (int u = 0; u < 8; u++) { si[u] = g_csr_src[e + u]; ni[u] = g_csr_norm[e + u]; }
        uint2 q[8];
#pragma unroll
        for (int u = 0; u < 8; u++) q[u] = H2[(size_t)si[u] * 32 + lane];
#pragma unroll
        for (int u = 0; u < 8; u++) {
            __half2* h = (__half2*)&q[u];
            float n = ni[u];
#pragma unroll
            for (int j = 0; j < 2; j++) {
                float2 f2 = __half22float2(h[j]);
                acc[2 * j] += n * f2.x; acc[2 * j + 1] += n * f2.y;
            }
        }
    }
    for (; e < e1; e++) {
        int s = g_csr_src[e];
        float nrm = g_csr_norm[e];
        uint2 q0 = H2[(size_t)s * 32 + lane];
        __half2* h0 = (__half2*)&q0;
#pragma unroll
        for (int j = 0; j < 2; j++) {
            float2 f2 = __half22float2(h0[j]);
            acc[2 * j] += nrm * f2.x; acc[2 * j + 1] += nrm * f2.y;
        }
    }

    uint2 o;
    __half2* ho = (__half2*)&o;
#pragma unroll
    for (int j = 0; j < 2; j++) ho[j] = __floats2half2_rn(acc[2 * j], acc[2 * j + 1]);
    ((uint2*)g_A16)[(size_t)v * 32 + lane] = o;
}

// ---------------- agg F=256: TWO warps per node (128 cols each, x8 unroll) ------

__global__ __launch_bounds__(256) void agg256_kernel() {
    int gw = (blockIdx.x * blockDim.x + threadIdx.x) >> 5;
    int lane = threadIdx.x & 31;
    int v = gw >> 1;
    int half = gw & 1;
    if (v >= NN) return;
    const uint2* H2 = (const uint2*)g_h16;
    const size_t rb = (size_t)v * 64 + half * 32;   // uint2 units

    float acc[4];
    float dv = g_dinv[v];
    float w = dv * dv;
    {
        uint2 q = H2[rb + lane];
        __half2* h = (__half2*)&q;
#pragma unroll
        for (int j = 0; j < 2; j++) {
            float2 f2 = __half22float2(h[j]);
            acc[2 * j] = w * f2.x; acc[2 * j + 1] = w * f2.y;
        }
    }

    int e0 = g_off[v], e1 = g_off[v + 1];
    int hoff = half * 32;
    int e = e0;
    for (; e + 8 <= e1; e += 8) {
        int si[8]; float ni[8];
#pragma unroll
        for (int u = 0; u < 8; u++) { si[u] = g_csr_src[e + u]; ni[u] = g_csr_norm[e + u]; }
        uint2 q[8];
#pragma unroll
        for (int u = 0; u < 8; u++) q[u] = H2[(size_t)si[u] * 64 + hoff + lane];
#pragma unroll
        for (int u = 0; u < 8; u++) {
            __half2* h = (__half2*)&q[u];
            float n = ni[u];
#pragma unroll
            for (int j = 0; j < 2; j++) {
                float2 f2 = __half22float2(h[j]);
                acc[2 * j] += n * f2.x; acc[2 * j + 1] += n * f2.y;
            }
        }
    }
    for (; e < e1; e++) {
        int s = g_csr_src[e];
        float nrm = g_csr_norm[e];
        uint2 q0 = H2[(size_t)s * 64 + hoff + lane];
        __half2* h0 = (__half2*)&q0;
#pragma unroll
        for (int j = 0; j < 2; j++) {
            float2 f2 = __half22float2(h0[j]);
            acc[2 * j] += nrm * f2.x; acc[2 * j + 1] += nrm * f2.y;
        }
    }

    uint2 o;
    __half2* ho = (__half2*)&o;
#pragma unroll
    for (int j = 0; j < 2; j++) ho[j] = __floats2half2_rn(acc[2 * j], acc[2 * j + 1]);
    ((uint2*)g_A16)[rb + lane] = o;
}

// ---------------- global max pool helper -----------------------------------------

__device__ __forceinline__ void atomicMaxF(float* a, float v) {
    if (v >= 0.f) atomicMax((int*)a, __float_as_int(v));
    else          atomicMin((unsigned int*)a, __float_as_uint(v));
}

// ---------------- mma.sync fp16 GEMM (single-pass W), cp.async double-buffered --
// BM=128, BN=128, BK=32; 8 warps (4x2), warp tile 32x64
// POOL=false: output fp16 -> g_h16.  POOL=true: segmented max -> g_pool (no store)

#define SA 40
#define SB 136
#define A_ST (128 * SA)
#define B_ST (32 * SB)
#define SO 132
#define GT_SMEM ((2 * A_ST + 2 * B_ST) * 2)

template <bool POOL>
__global__ __launch_bounds__(256) void gemm_mma(const float* __restrict__ bias,
                                                int relu, int K, int wl,
                                                const int* __restrict__ batch) {
    extern __shared__ unsigned short smem[];
    unsigned short* Aa = smem;
    unsigned short* Bh = Aa + 2 * A_ST;
    __shared__ float bs[128];
    __shared__ int sbatch[128];

    const unsigned short* GWh = g_Wh[wl];

    int tid = threadIdx.x, lane = tid & 31, wid = tid >> 5;
    int tm = blockIdx.x, tn = blockIdx.y;
    int wm = wid & 3, wn = wid >> 2;
    if (tid < 128) {
        bs[tid] = bias[tn * 128 + tid];
        if (POOL) {
            int v = tm * 128 + tid;
            sbatch[tid] = (v < NN) ? batch[v] : -1;
        }
    }

    float c[16][4];
#pragma unroll
    for (int i = 0; i < 16; i++)
#pragma unroll
        for (int j = 0; j < 4; j++) c[i][j] = 0.f;

    u32 sAa = smem_u32(Aa);
    u32 sBh = smem_u32(Bh);

    auto issue = [&](int st, int k0) {
#pragma unroll
        for (int i = 0; i < 2; i++) {
            int idx = tid + i * 256;
            int row = idx >> 2, cg = idx & 3;
            int grow = tm * 128 + row;
            u32 sz = (grow < NN) ? 16u : 0u;
            size_t gof = (size_t)grow * K + k0 + cg * 8;
            u32 dof = (u32)((st * A_ST + row * SA + cg * 8) * 2);
            cp16(sAa + dof, g_A16 + gof, sz);
        }
#pragma unroll
        for (int i = 0; i < 2; i++) {
            int idx = tid + i * 256;
            int row = idx >> 4, cg = idx & 15;
            size_t gof = (size_t)(k0 + row) * 256 + tn * 128 + cg * 8;
            u32 dof = (u32)((st * B_ST + row * SB + cg * 8) * 2);
            cp16(sBh + dof, GWh + gof, 16u);
        }
        cp_commit();
    };

    const int niter = K >> 5;
    issue(0, 0);
    for (int it = 0; it < niter; it++) {
        int cur = it & 1;
        if (it + 1 < niter) {
            issue((it + 1) & 1, (it + 1) << 5);
            cp_wait<1>();
        } else {
            cp_wait<0>();
        }
        __syncthreads();

        u32 aof = (u32)(cur * A_ST * 2), bof = (u32)(cur * B_ST * 2);
#pragma unroll
        for (int ks = 0; ks < 2; ks++) {
            u32 ah[2][4], bh[4][4];
            int ar = wm * 32 + (lane & 15);
            int ac = ks * 16 + (lane >> 4) * 8;
            ldmx4(ah[0], sAa + aof + (u32)((ar * SA + ac) * 2));
            ldmx4(ah[1], sAa + aof + (u32)(((ar + 16) * SA + ac) * 2));
            int br = ks * 16 + (lane & 15);
#pragma unroll
            for (int g = 0; g < 4; g++) {
                int bc = wn * 64 + g * 16 + (lane >> 4) * 8;
                ldmx4t(bh[g], sBh + bof + (u32)((br * SB + bc) * 2));
            }
#pragma unroll
            for (int mt = 0; mt < 2; mt++)
#pragma unroll
                for (int nt = 0; nt < 8; nt++) {
                    mma16816h(c[mt * 8 + nt], ah[mt], &bh[nt >> 1][(nt & 1) * 2]);
                }
        }
        __syncthreads();
    }

    if (!POOL) {
#pragma unroll
        for (int mt = 0; mt < 2; mt++) {
#pragma unroll
            for (int nt = 0; nt < 8; nt++) {
                int r0 = tm * 128 + wm * 32 + mt * 16 + (lane >> 2);
                int cl = wn * 64 + nt * 8 + (lane & 3) * 2;
                int col = tn * 128 + cl;
                float b0 = bs[cl], b1 = bs[cl + 1];
                float v0 = c[mt * 8 + nt][0] + b0;
                float v1 = c[mt * 8 + nt][1] + b1;
                float v2 = c[mt * 8 + nt][2] + b0;
                float v3 = c[mt * 8 + nt][3] + b1;
                if (relu) {
                    v0 = fmaxf(v0, 0.f); v1 = fmaxf(v1, 0.f);
                    v2 = fmaxf(v2, 0.f); v3 = fmaxf(v3, 0.f);
                }
                if (r0 < NN)
                    *(__half2*)(g_h16 + (size_t)r0 * 256 + col) = __floats2half2_rn(v0, v1);
                if (r0 + 8 < NN)
                    *(__half2*)(g_h16 + (size_t)(r0 + 8) * 256 + col) = __floats2half2_rn(v2, v3);
            }
        }
    } else {
        unsigned short* ot = smem;   // [128][SO]
#pragma unroll
        for (int mt = 0; mt < 2; mt++) {
#pragma unroll
            for (int nt = 0; nt < 8; nt++) {
                int lr = wm * 32 + mt * 16 + (lane >> 2);
                int cl = wn * 64 + nt * 8 + (lane & 3) * 2;
                float b0 = bs[cl], b1 = bs[cl + 1];
                *(__half2*)(ot + lr * SO + cl) =
                    __floats2half2_rn(c[mt * 8 + nt][0] + b0, c[mt * 8 + nt][1] + b1);
                *(__half2*)(ot + (lr + 8) * SO + cl) =
                    __floats2half2_rn(c[mt * 8 + nt][2] + b0, c[mt * 8 + nt][3] + b1);
            }
        }
        __syncthreads();

        int colp = tid & 127;
        int half = tid >> 7;
        int base = half * 64;
        if (tm * 128 + base < NN) {
            float m = -INFINITY;
            int cg = sbatch[base];
            for (int r = 0; r < 64; r++) {
                int lr = base + r;
                if (tm * 128 + lr >= NN) break;
                int g = sbatch[lr];
                if (g != cg) {
                    atomicMaxF(&g_pool[cg * 256 + tn * 128 + colp], m);
                    m = -INFINITY;
                    cg = g;
                }
                m = fmaxf(m, h2f_bits(ot[lr * SO + colp]));
            }
            atomicMaxF(&g_pool[cg * 256 + tn * 128 + colp], m);
        }
    }
}

// ---------------- dense head ----------------------------------------------------

__global__ __launch_bounds__(128) void head_kernel(const float* __restrict__ Wl2,
                                                   const float* __restrict__ bl2,
                                                   const float* __restrict__ Wl3,
                                                   const float* __restrict__ bl3,
                                                   const float* __restrict__ Wl,
                                                   const float* __restrict__ bl,
                                                   float* __restrict__ out) {
    __shared__ float gs[256];
    __shared__ float h2[128];
    __shared__ float h3[128];
    int g = blockIdx.x;
    int t = threadIdx.x;
    gs[t]       = g_pool[g * 256 + t];
    gs[t + 128] = g_pool[g * 256 + 128 + t];
    __syncthreads();
    float a = bl2[t];
    for (int k = 0; k < 256; k++) a += gs[k] * Wl2[k * 128 + t];
    h2[t] = fmaxf(a, 0.f);
    __syncthreads();
    float b = bl3[t];
    for (int k = 0; k < 128; k++) b += h2[k] * Wl3[k * 128 + t];
    h3[t] = fmaxf(b, 0.f);
    __syncthreads();
    if (t < 10) {
        float c = bl[t];
        for (int k = 0; k < 128; k++) c += h3[k] * Wl[k * 10 + t];
        out[g * 10 + t] = c;
    }
}

// ---------------- launch ---------------------------------------------------------

extern "C" void kernel_launch(void* const* d_in, const int* in_sizes, int n_in,
                              void* d_out, int out_size) {
    const float* x     = (const float*)d_in[0];
    const int*   ei    = (const int*)d_in[1];
    const int*   batch = (const int*)d_in[2];
    const float *W1 = (const float*)d_in[3],  *b1 = (const float*)d_in[4];
    const float *W2 = (const float*)d_in[5],  *b2 = (const float*)d_in[6];
    const float *W3 = (const float*)d_in[7],  *b3 = (const float*)d_in[8];
    const float *W4 = (const float*)d_in[9],  *b4 = (const float*)d_in[10];
    const float *Wl2 = (const float*)d_in[11], *bl2 = (const float*)d_in[12];
    const float *Wl3 = (const float*)d_in[13], *bl3 = (const float*)d_in[14];
    const float *Wl  = (const float*)d_in[15], *bl  = (const float*)d_in[16];
    float* out = (float*)d_out;

    const int* esrc = ei;
    const int* edst = ei + NE;

    cudaFuncSetAttribute(gemm_mma<false>, cudaFuncAttributeMaxDynamicSharedMemorySize, GT_SMEM);
    cudaFuncSetAttribute(gemm_mma<true>,  cudaFuncAttributeMaxDynamicSharedMemorySize, GT_SMEM);

    // preprocessing + weight conversion (conv_w_all also zeroes g_cnt)
    conv_w_all<<<(163840 + 255) / 256, 256>>>(W2, W3, W4);
    count_kernel<<<(NE + 255) / 256, 256>>>(edst);
    scan1_kernel<<<SCAN_B, 256>>>();
    finalize_kernel<<<SCAN_B, 256>>>();
    fill_kernel<<<(NE + 255) / 256, 256>>>(esrc, edst);

    const int AGG_GRID  = (NN + 7) / 8;        // warp per node
    const int AGG_GRID2 = (2 * NN + 7) / 8;    // two warps per node
    dim3 ggrid(TM, 2);

    // layer 1: fused agg9 + GEMM(9->128) + relu -> g_h16 (stride 128)
    layer1_kernel<<<AGG_GRID, 256>>>(x, W1, b1);

    // layer 2: agg(F=128) -> fp16 A ; mma GEMM K=128 -> g_h16 (stride 256)
    agg128_kernel<<<AGG_GRID, 256>>>();
    gemm_mma<false><<<ggrid, 256, GT_SMEM>>>(b2, 1, 128, 0, batch);

    // layer 3
    agg256_kernel<<<AGG_GRID2, 256>>>();
    gemm_mma<false><<<ggrid, 256, GT_SMEM>>>(b3, 1, 256, 1, batch);

    // layer 4: GEMM + fused segmented max-pool -> g_pool
    agg256_kernel<<<AGG_GRID2, 256>>>();
    gemm_mma<true><<<ggrid, 256, GT_SMEM>>>(b4, 0, 256, 2, batch);

    // head
    head_kernel<<<NG, 128>>>(Wl2, bl2, Wl3, bl3, Wl, bl, out);
}

// round 17
// speedup vs baseline: 1.0966x; 1.0966x over previous
#include <cuda_runtime.h>
#include <cuda_fp16.h>
#include <math.h>

#define NN 50000
#define NE 800000
#define NG 64
#define SCAN_B ((NN + 255) / 256)
#define TM ((NN + 127) / 128)   // 391 m-tiles

typedef unsigned long long u64;
typedef unsigned int u32;

// ---------------- scratch (device globals; no allocation allowed) -------------
__device__ __half g_h16[(size_t)NN * 256];   // layer activations, fp16
__device__ __half g_A16[(size_t)NN * 256];   // aggregated activations (GEMM A), fp16
__device__ float g_dinv[NN];
__device__ int   g_cnt[NN];
__device__ int   g_off[NN + 1];
__device__ int   g_cur[NN];
__device__ int   g_bsum[SCAN_B];
__device__ int2  g_csr[NE];                  // packed {src, norm bits}
__device__ float g_pool[NG * 256];
// fp16 weights per layer (0:W2 K=128, 1:W3, 2:W4)
__device__ unsigned short g_Wh[3][256 * 256];

// ---------------- PTX helpers ---------------------------------------------------

__device__ __forceinline__ u32 smem_u32(const void* p) {
    u32 a;
    asm("{ .reg .u64 t; cvta.to.shared.u64 t, %1; cvt.u32.u64 %0, t; }" : "=r"(a) : "l"(p));
    return a;
}
__device__ __forceinline__ void ldmx4(u32* r, u32 a) {
    asm volatile("ldmatrix.sync.aligned.m8n8.x4.shared.b16 {%0,%1,%2,%3}, [%4];"
                 : "=r"(r[0]), "=r"(r[1]), "=r"(r[2]), "=r"(r[3]) : "r"(a));
}
__device__ __forceinline__ void ldmx4t(u32* r, u32 a) {
    asm volatile("ldmatrix.sync.aligned.m8n8.x4.trans.shared.b16 {%0,%1,%2,%3}, [%4];"
                 : "=r"(r[0]), "=r"(r[1]), "=r"(r[2]), "=r"(r[3]) : "r"(a));
}
__device__ __forceinline__ void mma16816h(float* c, const u32* a, const u32* b) {
    asm volatile(
        "mma.sync.aligned.m16n8k16.row.col.f32.f16.f16.f32 "
        "{%0,%1,%2,%3}, {%4,%5,%6,%7}, {%8,%9}, {%0,%1,%2,%3};"
        : "+f"(c[0]), "+f"(c[1]), "+f"(c[2]), "+f"(c[3])
        : "r"(a[0]), "r"(a[1]), "r"(a[2]), "r"(a[3]), "r"(b[0]), "r"(b[1]));
}
__device__ __forceinline__ void cp16(u32 dst, const void* src, u32 sz) {
    asm volatile("cp.async.cg.shared.global [%0], [%1], 16, %2;"
                 :: "r"(dst), "l"(src), "r"(sz) : "memory");
}
__device__ __forceinline__ void cp_commit() {
    asm volatile("cp.async.commit_group;" ::: "memory");
}
template <int N>
__device__ __forceinline__ void cp_wait() {
    asm volatile("cp.async.wait_group %0;" :: "n"(N) : "memory");
}
__device__ __forceinline__ float h2f_bits(unsigned short bits) {
    __half h = __ushort_as_half(bits);
    return __half2float(h);
}

// ---------------- preprocessing ----------------------------------------------

__global__ void count_kernel(const int* __restrict__ dst) {
    int e = blockIdx.x * blockDim.x + threadIdx.x;
    if (e < NE) atomicAdd(&g_cnt[dst[e]], 1);
}

__global__ void scan1_kernel() {
    __shared__ int s[256];
    int tid = threadIdx.x;
    int idx = blockIdx.x * 256 + tid;
    int v = (idx < NN) ? g_cnt[idx] : 0;
    s[tid] = v;
    __syncthreads();
#pragma unroll
    for (int o = 1; o < 256; o <<= 1) {
        int t = (tid >= o) ? s[tid - o] : 0;
        __syncthreads();
        s[tid] += t;
        __syncthreads();
    }
    if (idx < NN) g_off[idx] = s[tid] - v;
    if (tid == 255) g_bsum[blockIdx.x] = s[255];
}

// finalize with inline block-base reduction
__global__ void finalize_kernel() {
    __shared__ int s[256];
    int tid = threadIdx.x;
    int b = blockIdx.x;
    int part = (tid < SCAN_B && tid < b) ? g_bsum[tid] : 0;
    s[tid] = part;
    __syncthreads();
#pragma unroll
    for (int o = 128; o > 0; o >>= 1) {
        if (tid < o) s[tid] += s[tid + o];
        __syncthreads();
    }
    int base = s[0];

    int v = b * 256 + tid;
    if (v < NN) {
        int off = g_off[v] + base;
        g_off[v] = off;
        g_cur[v] = off;
        g_dinv[v] = rsqrtf((float)g_cnt[v] + 1.0f);
    }
    if (v < NG * 256) g_pool[v] = -INFINITY;
    if (v == 0) g_off[NN] = NE;
}

__global__ void fill_kernel(const int* __restrict__ src,
                            const int* __restrict__ dst) {
    int e = blockIdx.x * blockDim.x + threadIdx.x;
    if (e < NE) {
        int s = src[e];
        int d = dst[e];
        int pos = atomicAdd(&g_cur[d], 1);
        float nrm = g_dinv[s] * g_dinv[d];
        g_csr[pos] = make_int2(s, __float_as_int(nrm));
    }
}

// ---------------- weight conversion (fp16) + zero counters ----------------------

__global__ void conv_w_all(const float* __restrict__ W2,
                           const float* __restrict__ W3,
                           const float* __restrict__ W4) {
    int i = blockIdx.x * 256 + threadIdx.x;
    if (i < NN) g_cnt[i] = 0;
    const float* W;
    unsigned short* dh;
    int off;
    if (i < 32768)       { W = W2; off = i;           dh = g_Wh[0]; }
    else if (i < 98304)  { W = W3; off = i - 32768;   dh = g_Wh[1]; }
    else if (i < 163840) { W = W4; off = i - 98304;   dh = g_Wh[2]; }
    else return;
    dh[off] = __half_as_ushort(__float2half_rn(W[off]));
}

// ---------------- fused layer 1: agg9 + [N,9]@[9,128] + bias + relu -> fp16 -----

__global__ __launch_bounds__(256) void layer1_kernel(const float* __restrict__ x,
                                                     const float* __restrict__ W1,
                                                     const float* __restrict__ b1) {
    __shared__ float Ws[9 * 128];
    __shared__ float Bs[128];
    int tid = threadIdx.x;
    for (int i = tid; i < 9 * 128; i += 256) Ws[i] = W1[i];
    if (tid < 128) Bs[tid] = b1[tid];
    __syncthreads();

    int warp = (blockIdx.x * 256 + tid) >> 5;
    int lane = tid & 31;
    if (warp >= NN) return;
    int v = warp;
    float dv = g_dinv[v];
    float acc = 0.f;
    if (lane < 9) acc = dv * dv * x[v * 9 + lane];
    int e0 = g_off[v], e1 = g_off[v + 1];
    for (int e = e0; e < e1; e++) {
        int2 ed = g_csr[e];
        float nrm = __int_as_float(ed.y);
        if (lane < 9) acc += nrm * x[ed.x * 9 + lane];
    }
    float ak[9];
#pragma unroll
    for (int k = 0; k < 9; k++) ak[k] = __shfl_sync(0xffffffffu, acc, k);

    int f = lane * 4;
    float o0 = Bs[f], o1 = Bs[f + 1], o2 = Bs[f + 2], o3 = Bs[f + 3];
#pragma unroll
    for (int k = 0; k < 9; k++) {
        float a = ak[k];
        const float* wr = &Ws[k * 128 + f];
        o0 += a * wr[0]; o1 += a * wr[1]; o2 += a * wr[2]; o3 += a * wr[3];
    }
    o0 = fmaxf(o0, 0.f); o1 = fmaxf(o1, 0.f);
    o2 = fmaxf(o2, 0.f); o3 = fmaxf(o3, 0.f);
    __half2* dst = (__half2*)(g_h16 + (size_t)v * 128 + f);
    dst[0] = __floats2half2_rn(o0, o1);
    dst[1] = __floats2half2_rn(o2, o3);
}

// ---------------- aggregation: warp per node, gather fp16 rows (x8 unroll) ------

template <int F>
__global__ __launch_bounds__(256) void agg_f16() {
    int warp = (blockIdx.x * blockDim.x + threadIdx.x) >> 5;
    int lane = threadIdx.x & 31;
    if (warp >= NN) return;
    const int v = warp;

    float acc[F / 32];
    float dv = g_dinv[v];
    float w = dv * dv;
    if (F == 256) {
        uint4 q = ((const uint4*)g_h16)[(size_t)v * 32 + lane];
        __half2* h = (__half2*)&q;
#pragma unroll
        for (int j = 0; j < 4; j++) {
            float2 f2 = __half22float2(h[j]);
            acc[2 * j] = w * f2.x; acc[2 * j + 1] = w * f2.y;
        }
    } else {
        uint2 q = ((const uint2*)g_h16)[(size_t)v * 32 + lane];
        __half2* h = (__half2*)&q;
#pragma unroll
        for (int j = 0; j < 2; j++) {
            float2 f2 = __half22float2(h[j]);
            acc[2 * j] = w * f2.x; acc[2 * j + 1] = w * f2.y;
        }
    }

    int e0 = g_off[v], e1 = g_off[v + 1];
    int e = e0;
    for (; e + 8 <= e1; e += 8) {
        int2 ed[8];
#pragma unroll
        for (int u = 0; u < 8; u++) ed[u] = g_csr[e + u];
        if (F == 256) {
            uint4 q[8];
#pragma unroll
            for (int u = 0; u < 8; u++) q[u] = ((const uint4*)g_h16)[(size_t)ed[u].x * 32 + lane];
#pragma unroll
            for (int u = 0; u < 8; u++) {
                __half2* h = (__half2*)&q[u];
                float n = __int_as_float(ed[u].y);
#pragma unroll
                for (int j = 0; j < 4; j++) {
                    float2 f2 = __half22float2(h[j]);
                    acc[2 * j] += n * f2.x; acc[2 * j + 1] += n * f2.y;
                }
            }
        } else {
            uint2 q[8];
#pragma unroll
            for (int u = 0; u < 8; u++) q[u] = ((const uint2*)g_h16)[(size_t)ed[u].x * 32 + lane];
#pragma unroll
            for (int u = 0; u < 8; u++) {
                __half2* h = (__half2*)&q[u];
                float n = __int_as_float(ed[u].y);
#pragma unroll
                for (int j = 0; j < 2; j++) {
                    float2 f2 = __half22float2(h[j]);
                    acc[2 * j] += n * f2.x; acc[2 * j + 1] += n * f2.y;
                }
            }
        }
    }
    for (; e < e1; e++) {
        int2 ed = g_csr[e];
        float nrm = __int_as_float(ed.y);
        if (F == 256) {
            uint4 q0 = ((const uint4*)g_h16)[(size_t)ed.x * 32 + lane];
            __half2* h0 = (__half2*)&q0;
#pragma unroll
            for (int j = 0; j < 4; j++) {
                float2 f2 = __half22float2(h0[j]);
                acc[2 * j] += nrm * f2.x; acc[2 * j + 1] += nrm * f2.y;
            }
        } else {
            uint2 q0 = ((const uint2*)g_h16)[(size_t)ed.x * 32 + lane];
            __half2* h0 = (__half2*)&q0;
#pragma unroll
            for (int j = 0; j < 2; j++) {
                float2 f2 = __half22float2(h0[j]);
                acc[2 * j] += nrm * f2.x; acc[2 * j + 1] += nrm * f2.y;
            }
        }
    }

    if (F == 256) {
        uint4 o;
        __half2* ho = (__half2*)&o;
#pragma unroll
        for (int j = 0; j < 4; j++) ho[j] = __floats2half2_rn(acc[2 * j], acc[2 * j + 1]);
        ((uint4*)g_A16)[(size_t)v * 32 + lane] = o;
    } else {
        uint2 o;
        __half2* ho = (__half2*)&o;
#pragma unroll
        for (int j = 0; j < 2; j++) ho[j] = __floats2half2_rn(acc[2 * j], acc[2 * j + 1]);
        ((uint2*)g_A16)[(size_t)v * 32 + lane] = o;
    }
}

// ---------------- global max pool helper -----------------------------------------

__device__ __forceinline__ void atomicMaxF(float* a, float v) {
    if (v >= 0.f) atomicMax((int*)a, __float_as_int(v));
    else          atomicMin((unsigned int*)a, __float_as_uint(v));
}

// ---------------- mma.sync fp16 GEMM (single-pass W), cp.async double-buffered --

#define SA 40
#define SB 136
#define A_ST (128 * SA)
#define B_ST (32 * SB)
#define SO 132
#define GT_SMEM ((2 * A_ST + 2 * B_ST) * 2)

template <bool POOL>
__global__ __launch_bounds__(256) void gemm_mma(const float* __restrict__ bias,
                                                int relu, int K, int wl,
                                                const int* __restrict__ batch) {
    extern __shared__ unsigned short smem[];
    unsigned short* Aa = smem;
    unsigned short* Bh = Aa + 2 * A_ST;
    __shared__ float bs[128];
    __shared__ int sbatch[128];

    const unsigned short* GWh = g_Wh[wl];

    int tid = threadIdx.x, lane = tid & 31, wid = tid >> 5;
    int tm = blockIdx.x, tn = blockIdx.y;
    int wm = wid & 3, wn = wid >> 2;
    if (tid < 128) {
        bs[tid] = bias[tn * 128 + tid];
        if (POOL) {
            int v = tm * 128 + tid;
            sbatch[tid] = (v < NN) ? batch[v] : -1;
        }
    }

    float c[16][4];
#pragma unroll
    for (int i = 0; i < 16; i++)
#pragma unroll
        for (int j = 0; j < 4; j++) c[i][j] = 0.f;

    u32 sAa = smem_u32(Aa);
    u32 sBh = smem_u32(Bh);

    auto issue = [&](int st, int k0) {
#pragma unroll
        for (int i = 0; i < 2; i++) {
            int idx = tid + i * 256;
            int row = idx >> 2, cg = idx & 3;
            int grow = tm * 128 + row;
            u32 sz = (grow < NN) ? 16u : 0u;
            size_t gof = (size_t)grow * K + k0 + cg * 8;
            u32 dof = (u32)((st * A_ST + row * SA + cg * 8) * 2);
            cp16(sAa + dof, g_A16 + gof, sz);
        }
#pragma unroll
        for (int i = 0; i < 2; i++) {
            int idx = tid + i * 256;
            int row = idx >> 4, cg = idx & 15;
            size_t gof = (size_t)(k0 + row) * 256 + tn * 128 + cg * 8;
            u32 dof = (u32)((st * B_ST + row * SB + cg * 8) * 2);
            cp16(sBh + dof, GWh + gof, 16u);
        }
        cp_commit();
    };

    const int niter = K >> 5;
    issue(0, 0);
    for (int it = 0; it < niter; it++) {
        int cur = it & 1;
        if (it + 1 < niter) {
            issue((it + 1) & 1, (it + 1) << 5);
            cp_wait<1>();
        } else {
            cp_wait<0>();
        }
        __syncthreads();

        u32 aof = (u32)(cur * A_ST * 2), bof = (u32)(cur * B_ST * 2);
#pragma unroll
        for (int ks = 0; ks < 2; ks++) {
            u32 ah[2][4], bh[4][4];
            int ar = wm * 32 + (lane & 15);
            int ac = ks * 16 + (lane >> 4) * 8;
            ldmx4(ah[0], sAa + aof + (u32)((ar * SA + ac) * 2));
            ldmx4(ah[1], sAa + aof + (u32)(((ar + 16) * SA + ac) * 2));
            int br = ks * 16 + (lane & 15);
#pragma unroll
            for (int g = 0; g < 4; g++) {
                int bc = wn * 64 + g * 16 + (lane >> 4) * 8;
                ldmx4t(bh[g], sBh + bof + (u32)((br * SB + bc) * 2));
            }
#pragma unroll
            for (int mt = 0; mt < 2; mt++)
#pragma unroll
                for (int nt = 0; nt < 8; nt++) {
                    mma16816h(c[mt * 8 + nt], ah[mt], &bh[nt >> 1][(nt & 1) * 2]);
                }
        }
        __syncthreads();
    }

    if (!POOL) {
#pragma unroll
        for (int mt = 0; mt < 2; mt++) {
#pragma unroll
            for (int nt = 0; nt < 8; nt++) {
                int r0 = tm * 128 + wm * 32 + mt * 16 + (lane >> 2);
                int cl = wn * 64 + nt * 8 + (lane & 3) * 2;
                int col = tn * 128 + cl;
                float b0 = bs[cl], b1 = bs[cl + 1];
                float v0 = c[mt * 8 + nt][0] + b0;
                float v1 = c[mt * 8 + nt][1] + b1;
                float v2 = c[mt * 8 + nt][2] + b0;
                float v3 = c[mt * 8 + nt][3] + b1;
                if (relu) {
                    v0 = fmaxf(v0, 0.f); v1 = fmaxf(v1, 0.f);
                    v2 = fmaxf(v2, 0.f); v3 = fmaxf(v3, 0.f);
                }
                if (r0 < NN)
                    *(__half2*)(g_h16 + (size_t)r0 * 256 + col) = __floats2half2_rn(v0, v1);
                if (r0 + 8 < NN)
                    *(__half2*)(g_h16 + (size_t)(r0 + 8) * 256 + col) = __floats2half2_rn(v2, v3);
            }
        }
    } else {
        unsigned short* ot = smem;   // [128][SO]
#pragma unroll
        for (int mt = 0; mt < 2; mt++) {
#pragma unroll
            for (int nt = 0; nt < 8; nt++) {
                int lr = wm * 32 + mt * 16 + (lane >> 2);
                int cl = wn * 64 + nt * 8 + (lane & 3) * 2;
                float b0 = bs[cl], b1 = bs[cl + 1];
                *(__half2*)(ot + lr * SO + cl) =
                    __floats2half2_rn(c[mt * 8 + nt][0] + b0, c[mt * 8 + nt][1] + b1);
                *(__half2*)(ot + (lr + 8) * SO + cl) =
                    __floats2half2_rn(c[mt * 8 + nt][2] + b0, c[mt * 8 + nt][3] + b1);
            }
        }
        __syncthreads();

        int colp = tid & 127;
        int half = tid >> 7;
        int base = half * 64;
        if (tm * 128 + base < NN) {
            float m = -INFINITY;
            int cg = sbatch[base];
            for (int r = 0; r < 64; r++) {
                int lr = base + r;
                if (tm * 128 + lr >= NN) break;
                int g = sbatch[lr];
                if (g != cg) {
                    atomicMaxF(&g_pool[cg * 256 + tn * 128 + colp], m);
                    m = -INFINITY;
                    cg = g;
                }
                m = fmaxf(m, h2f_bits(ot[lr * SO + colp]));
            }
            atomicMaxF(&g_pool[cg * 256 + tn * 128 + colp], m);
        }
    }
}

// ---------------- dense head ----------------------------------------------------

__global__ __launch_bounds__(128) void head_kernel(const float* __restrict__ Wl2,
                                                   const float* __restrict__ bl2,
                                                   const float* __restrict__ Wl3,
                                                   const float* __restrict__ bl3,
                                                   const float* __restrict__ Wl,
                                                   const float* __restrict__ bl,
                                                   float* __restrict__ out) {
    __shared__ float gs[256];
    __shared__ float h2[128];
    __shared__ float h3[128];
    int g = blockIdx.x;
    int t = threadIdx.x;
    gs[t]       = g_pool[g * 256 + t];
    gs[t + 128] = g_pool[g * 256 + 128 + t];
    __syncthreads();
    float a = bl2[t];
    for (int k = 0; k < 256; k++) a += gs[k] * Wl2[k * 128 + t];
    h2[t] = fmaxf(a, 0.f);
    __syncthreads();
    float b = bl3[t];
    for (int k = 0; k < 128; k++) b += h2[k] * Wl3[k * 128 + t];
    h3[t] = fmaxf(b, 0.f);
    __syncthreads();
    if (t < 10) {
        float c = bl[t];
        for (int k = 0; k < 128; k++) c += h3[k] * Wl[k * 10 + t];
        out[g * 10 + t] = c;
    }
}

// ---------------- launch ---------------------------------------------------------

extern "C" void kernel_launch(void* const* d_in, const int* in_sizes, int n_in,
                              void* d_out, int out_size) {
    const float* x     = (const float*)d_in[0];
    const int*   ei    = (const int*)d_in[1];
    const int*   batch = (const int*)d_in[2];
    const float *W1 = (const float*)d_in[3],  *b1 = (const float*)d_in[4];
    const float *W2 = (const float*)d_in[5],  *b2 = (const float*)d_in[6];
    const float *W3 = (const float*)d_in[7],  *b3 = (const float*)d_in[8];
    const float *W4 = (const float*)d_in[9],  *b4 = (const float*)d_in[10];
    const float *Wl2 = (const float*)d_in[11], *bl2 = (const float*)d_in[12];
    const float *Wl3 = (const float*)d_in[13], *bl3 = (const float*)d_in[14];
    const float *Wl  = (const float*)d_in[15], *bl  = (const float*)d_in[16];
    float* out = (float*)d_out;

    const int* esrc = ei;
    const int* edst = ei + NE;

    cudaFuncSetAttribute(gemm_mma<false>, cudaFuncAttributeMaxDynamicSharedMemorySize, GT_SMEM);
    cudaFuncSetAttribute(gemm_mma<true>,  cudaFuncAttributeMaxDynamicSharedMemorySize, GT_SMEM);

    // preprocessing + weight conversion (conv_w_all also zeroes g_cnt)
    conv_w_all<<<(163840 + 255) / 256, 256>>>(W2, W3, W4);
    count_kernel<<<(NE + 255) / 256, 256>>>(edst);
    scan1_kernel<<<SCAN_B, 256>>>();
    finalize_kernel<<<SCAN_B, 256>>>();
    fill_kernel<<<(NE + 255) / 256, 256>>>(esrc, edst);

    const int AGG_GRID = (NN + 7) / 8;   // warp per node
    dim3 ggrid(TM, 2);

    // layer 1: fused agg9 + GEMM(9->128) + relu -> g_h16 (stride 128)
    layer1_kernel<<<AGG_GRID, 256>>>(x, W1, b1);

    // layer 2: agg(F=128) -> fp16 A ; mma GEMM K=128 -> g_h16 (stride 256)
    agg_f16<128><<<AGG_GRID, 256>>>();
    gemm_mma<false><<<ggrid, 256, GT_SMEM>>>(b2, 1, 128, 0, batch);

    // layer 3
    agg_f16<256><<<AGG_GRID, 256>>>();
    gemm_mma<false><<<ggrid, 256, GT_SMEM>>>(b3, 1, 256, 1, batch);

    // layer 4: GEMM + fused segmented max-pool -> g_pool
    agg_f16<256><<<AGG_GRID, 256>>>();
    gemm_mma<true><<<ggrid, 256, GT_SMEM>>>(b4, 0, 256, 2, batch);

    // head
    head_kernel<<<NG, 128>>>(Wl2, bl2, Wl3, bl3, Wl, bl, out);
}